// round 6
// baseline (speedup 1.0000x reference)
#include <cuda_runtime.h>

#define R_ROWS 4194304
#define ROWS_PER_BLOCK 1024
#define NBLK (R_ROWS / ROWS_PER_BLOCK)   // 4096
#define THREADS 256
#define ITEMS 4                          // rows per thread (blocked -> stable order)

#define N5 (R_ROWS * 5u)                 // 20971520 floats (rois)
#define N6 (R_ROWS * 6u)                 // 25165824 floats (rois_full)
#define TOTAL_OUT (N5 + N6 + 2u)         // 46137346

__device__ int g_cntA[NBLK];
__device__ int g_cntB[NBLK];
__device__ int g_offA[NBLK];
__device__ int g_offB[NBLK];
__device__ int g_tot[2];

// ---------------------------------------------------------------------------
// Pass 1: per-block predicate counts. Stage rows in SMEM (coalesced float4).
// ---------------------------------------------------------------------------
__global__ __launch_bounds__(THREADS) void count_kernel(const float* __restrict__ det) {
    __shared__ float4 s4[ROWS_PER_BLOCK * 6 / 4];   // 24 KB
    __shared__ int wred[THREADS / 32];

    const int blk = blockIdx.x;
    const float4* src = (const float4*)(det + (size_t)blk * ROWS_PER_BLOCK * 6);
    #pragma unroll
    for (int i = threadIdx.x; i < ROWS_PER_BLOCK * 6 / 4; i += THREADS)
        s4[i] = src[i];
    __syncthreads();

    const float* sr = (const float*)s4;
    const int r0 = threadIdx.x * ITEMS;
    int cA = 0, cB = 0;
    #pragma unroll
    for (int j = 0; j < ITEMS; j++) {
        float c  = sr[(r0 + j) * 6 + 0];
        float sc = sr[(r0 + j) * 6 + 5];
        bool b = (sc >= 0.35f);
        bool a = b && (c == 0.0f);
        cA += a; cB += b;
    }

    int packed = (cA << 16) | cB;   // per-block sums <= 1024, no carry
    #pragma unroll
    for (int d = 16; d > 0; d >>= 1)
        packed += __shfl_down_sync(0xffffffffu, packed, d);
    const int lane = threadIdx.x & 31, w = threadIdx.x >> 5;
    if (lane == 0) wred[w] = packed;
    __syncthreads();
    if (threadIdx.x == 0) {
        int s = 0;
        #pragma unroll
        for (int i = 0; i < THREADS / 32; i++) s += wred[i];
        g_cntA[blk] = s >> 16;
        g_cntB[blk] = s & 0xffff;
    }
}

// ---------------------------------------------------------------------------
// Scan: one block, 1024 threads, 4 counts each (NBLK=4096). A<<32 | B packed.
// ---------------------------------------------------------------------------
__global__ __launch_bounds__(1024) void scan_kernel() {
    __shared__ unsigned long long wsum[32];
    const int t = threadIdx.x;
    const int lane = t & 31, w = t >> 5;

    unsigned long long v[4];
    unsigned long long tsum = 0;
    #pragma unroll
    for (int j = 0; j < 4; j++) {
        int i = t * 4 + j;
        v[j] = ((unsigned long long)(unsigned)g_cntA[i] << 32) | (unsigned)g_cntB[i];
        tsum += v[j];
    }

    unsigned long long inc = tsum;
    #pragma unroll
    for (int d = 1; d < 32; d <<= 1) {
        unsigned long long o = __shfl_up_sync(0xffffffffu, inc, d);
        if (lane >= d) inc += o;
    }
    if (lane == 31) wsum[w] = inc;
    __syncthreads();
    if (w == 0) {
        unsigned long long x = wsum[lane];
        #pragma unroll
        for (int d = 1; d < 32; d <<= 1) {
            unsigned long long o = __shfl_up_sync(0xffffffffu, x, d);
            if (lane >= d) x += o;
        }
        wsum[lane] = x;   // inclusive warp totals
    }
    __syncthreads();

    unsigned long long base = (w > 0 ? wsum[w - 1] : 0ull) + (inc - tsum); // exclusive
    #pragma unroll
    for (int j = 0; j < 4; j++) {
        int i = t * 4 + j;
        g_offA[i] = (int)(base >> 32);
        g_offB[i] = (int)(base & 0xffffffffull);
        base += v[j];
    }
    if (t == 1023) {
        g_tot[0] = (int)(base >> 32);
        g_tot[1] = (int)(base & 0xffffffffull);
    }
}

// ---------------------------------------------------------------------------
// Pass 2: stable scatter. Intra-block scan of packed (cntA<<16|cntB).
// ---------------------------------------------------------------------------
__global__ __launch_bounds__(THREADS) void scatter_kernel(const float* __restrict__ det,
                                                          float* __restrict__ out) {
    __shared__ float4 s4[ROWS_PER_BLOCK * 6 / 4];   // 24 KB
    __shared__ int wsum[THREADS / 32];

    const int blk = blockIdx.x;
    const float4* src = (const float4*)(det + (size_t)blk * ROWS_PER_BLOCK * 6);
    #pragma unroll
    for (int i = threadIdx.x; i < ROWS_PER_BLOCK * 6 / 4; i += THREADS)
        s4[i] = src[i];
    __syncthreads();

    const float* sr = (const float*)s4;
    const int r0 = threadIdx.x * ITEMS;

    float2 vrow[ITEMS][3];
    bool pa[ITEMS], pb[ITEMS];
    int cA = 0, cB = 0;
    #pragma unroll
    for (int j = 0; j < ITEMS; j++) {
        const float2* rp = (const float2*)(sr + (r0 + j) * 6);
        vrow[j][0] = rp[0];
        vrow[j][1] = rp[1];
        vrow[j][2] = rp[2];
        bool b = (vrow[j][2].y >= 0.35f);          // score
        bool a = b && (vrow[j][0].x == 0.0f);      // class id
        pa[j] = a; pb[j] = b;
        cA += a; cB += b;
    }

    int packed = (cA << 16) | cB;
    int incp = packed;
    const int lane = threadIdx.x & 31, w = threadIdx.x >> 5;
    #pragma unroll
    for (int d = 1; d < 32; d <<= 1) {
        int o = __shfl_up_sync(0xffffffffu, incp, d);
        if (lane >= d) incp += o;
    }
    if (lane == 31) wsum[w] = incp;
    __syncthreads();
    int wbase = 0;
    #pragma unroll
    for (int i = 0; i < THREADS / 32; i++)
        if (i < w) wbase += wsum[i];
    const int exc = wbase + incp - packed;   // exclusive prefix for this thread

    int dA = g_offA[blk] + (exc >> 16);
    int dB = g_offB[blk] + (exc & 0xffff);

    float* outFull = out + (size_t)N5;
    #pragma unroll
    for (int j = 0; j < ITEMS; j++) {
        if (pb[j]) {
            float2* o = (float2*)(outFull + (size_t)dB * 6);  // 24B stride -> 8B aligned
            o[0] = vrow[j][0];
            o[1] = vrow[j][1];
            o[2] = vrow[j][2];
            dB++;
        }
        if (pa[j]) {
            float* o = out + (size_t)dA * 5;
            o[0] = 0.0f;
            o[1] = vrow[j][0].y;
            o[2] = vrow[j][1].x;
            o[3] = vrow[j][1].y;
            o[4] = vrow[j][2].x;
            dA++;
        }
    }
}

// ---------------------------------------------------------------------------
// Fill: zero the tails (dest_row >= n) and write the two count scalars.
// ---------------------------------------------------------------------------
__global__ __launch_bounds__(256) void fill_kernel(float* __restrict__ out) {
    const unsigned idx = blockIdx.x * 256u + threadIdx.x;
    if (idx >= TOTAL_OUT) return;
    const int nA = g_tot[0];
    const int nB = g_tot[1];
    if (idx < N5) {
        unsigned row = idx / 5u;
        if ((int)row >= nA) out[idx] = 0.0f;
    } else if (idx < N5 + N6) {
        unsigned u = idx - N5;
        unsigned row = u / 6u;
        if ((int)row >= nB) out[idx] = 0.0f;
    } else if (idx == N5 + N6) {
        out[idx] = (float)nA;
    } else {
        out[idx] = (float)nB;
    }
}

extern "C" void kernel_launch(void* const* d_in, const int* in_sizes, int n_in,
                              void* d_out, int out_size) {
    const float* det = (const float*)d_in[0];
    float* out = (float*)d_out;

    count_kernel<<<NBLK, THREADS>>>(det);
    scan_kernel<<<1, 1024>>>();
    scatter_kernel<<<NBLK, THREADS>>>(det, out);
    fill_kernel<<<(TOTAL_OUT + 255u) / 256u, 256>>>(out);
}

// round 9
// speedup vs baseline: 1.7395x; 1.7395x over previous
#include <cuda_runtime.h>

#define R_ROWS 4194304
#define ROWS_PER_BLOCK 1024
#define NBLK (R_ROWS / ROWS_PER_BLOCK)   // 4096
#define THREADS 256
#define ITEMS 4                          // rows per thread (blocked -> stable order)

#define N5 (R_ROWS * 5u)                 // 20971520 floats (rois)
#define N6 (R_ROWS * 6u)                 // 25165824 floats (rois_full)
#define TOTAL_OUT (N5 + N6 + 2u)         // 46137346

__device__ int g_cntA[NBLK];
__device__ int g_cntB[NBLK];
__device__ int g_offA[NBLK];
__device__ int g_offB[NBLK];
__device__ int g_tot[2];

// ---------------------------------------------------------------------------
// Pass 1: per-block predicate counts. Stage rows in SMEM (coalesced float4).
// ---------------------------------------------------------------------------
__global__ __launch_bounds__(THREADS) void count_kernel(const float* __restrict__ det) {
    __shared__ float4 s4[ROWS_PER_BLOCK * 6 / 4];   // 24 KB
    __shared__ int wred[THREADS / 32];

    const int blk = blockIdx.x;
    const float4* src = (const float4*)(det + (size_t)blk * ROWS_PER_BLOCK * 6);
    #pragma unroll
    for (int i = threadIdx.x; i < ROWS_PER_BLOCK * 6 / 4; i += THREADS)
        s4[i] = src[i];
    __syncthreads();

    const float* sr = (const float*)s4;
    const int r0 = threadIdx.x * ITEMS;
    int cA = 0, cB = 0;
    #pragma unroll
    for (int j = 0; j < ITEMS; j++) {
        float c  = sr[(r0 + j) * 6 + 0];
        float sc = sr[(r0 + j) * 6 + 5];
        bool b = (sc >= 0.35f);
        bool a = b && (c == 0.0f);
        cA += a; cB += b;
    }

    int packed = (cA << 16) | cB;   // per-block sums <= 1024, no carry
    #pragma unroll
    for (int d = 16; d > 0; d >>= 1)
        packed += __shfl_down_sync(0xffffffffu, packed, d);
    const int lane = threadIdx.x & 31, w = threadIdx.x >> 5;
    if (lane == 0) wred[w] = packed;
    __syncthreads();
    if (threadIdx.x == 0) {
        int s = 0;
        #pragma unroll
        for (int i = 0; i < THREADS / 32; i++) s += wred[i];
        g_cntA[blk] = s >> 16;
        g_cntB[blk] = s & 0xffff;
    }
}

// ---------------------------------------------------------------------------
// Scan: one block, 1024 threads, 4 counts each (NBLK=4096). A<<32 | B packed.
// ---------------------------------------------------------------------------
__global__ __launch_bounds__(1024) void scan_kernel() {
    __shared__ unsigned long long wsum[32];
    const int t = threadIdx.x;
    const int lane = t & 31, w = t >> 5;

    unsigned long long v[4];
    unsigned long long tsum = 0;
    #pragma unroll
    for (int j = 0; j < 4; j++) {
        int i = t * 4 + j;
        v[j] = ((unsigned long long)(unsigned)g_cntA[i] << 32) | (unsigned)g_cntB[i];
        tsum += v[j];
    }

    unsigned long long inc = tsum;
    #pragma unroll
    for (int d = 1; d < 32; d <<= 1) {
        unsigned long long o = __shfl_up_sync(0xffffffffu, inc, d);
        if (lane >= d) inc += o;
    }
    if (lane == 31) wsum[w] = inc;
    __syncthreads();
    if (w == 0) {
        unsigned long long x = wsum[lane];
        #pragma unroll
        for (int d = 1; d < 32; d <<= 1) {
            unsigned long long o = __shfl_up_sync(0xffffffffu, x, d);
            if (lane >= d) x += o;
        }
        wsum[lane] = x;   // inclusive warp totals
    }
    __syncthreads();

    unsigned long long base = (w > 0 ? wsum[w - 1] : 0ull) + (inc - tsum); // exclusive
    #pragma unroll
    for (int j = 0; j < 4; j++) {
        int i = t * 4 + j;
        g_offA[i] = (int)(base >> 32);
        g_offB[i] = (int)(base & 0xffffffffull);
        base += v[j];
    }
    if (t == 1023) {
        g_tot[0] = (int)(base >> 32);
        g_tot[1] = (int)(base & 0xffffffffull);
    }
}

// ---------------------------------------------------------------------------
// Pass 2: stable scatter. Intra-block scan of packed (cntA<<16|cntB).
// ---------------------------------------------------------------------------
__global__ __launch_bounds__(THREADS) void scatter_kernel(const float* __restrict__ det,
                                                          float* __restrict__ out) {
    __shared__ float4 s4[ROWS_PER_BLOCK * 6 / 4];   // 24 KB
    __shared__ int wsum[THREADS / 32];

    const int blk = blockIdx.x;
    const float4* src = (const float4*)(det + (size_t)blk * ROWS_PER_BLOCK * 6);
    #pragma unroll
    for (int i = threadIdx.x; i < ROWS_PER_BLOCK * 6 / 4; i += THREADS)
        s4[i] = src[i];
    __syncthreads();

    const float* sr = (const float*)s4;
    const int r0 = threadIdx.x * ITEMS;

    float2 vrow[ITEMS][3];
    bool pa[ITEMS], pb[ITEMS];
    int cA = 0, cB = 0;
    #pragma unroll
    for (int j = 0; j < ITEMS; j++) {
        const float2* rp = (const float2*)(sr + (r0 + j) * 6);
        vrow[j][0] = rp[0];
        vrow[j][1] = rp[1];
        vrow[j][2] = rp[2];
        bool b = (vrow[j][2].y >= 0.35f);          // score
        bool a = b && (vrow[j][0].x == 0.0f);      // class id
        pa[j] = a; pb[j] = b;
        cA += a; cB += b;
    }

    int packed = (cA << 16) | cB;
    int incp = packed;
    const int lane = threadIdx.x & 31, w = threadIdx.x >> 5;
    #pragma unroll
    for (int d = 1; d < 32; d <<= 1) {
        int o = __shfl_up_sync(0xffffffffu, incp, d);
        if (lane >= d) incp += o;
    }
    if (lane == 31) wsum[w] = incp;
    __syncthreads();
    int wbase = 0;
    #pragma unroll
    for (int i = 0; i < THREADS / 32; i++)
        if (i < w) wbase += wsum[i];
    const int exc = wbase + incp - packed;   // exclusive prefix for this thread

    int dA = g_offA[blk] + (exc >> 16);
    int dB = g_offB[blk] + (exc & 0xffff);

    float* outFull = out + (size_t)N5;
    #pragma unroll
    for (int j = 0; j < ITEMS; j++) {
        if (pb[j]) {
            float2* o = (float2*)(outFull + (size_t)dB * 6);  // 24B stride -> 8B aligned
            o[0] = vrow[j][0];
            o[1] = vrow[j][1];
            o[2] = vrow[j][2];
            dB++;
        }
        if (pa[j]) {
            float* o = out + (size_t)dA * 5;
            o[0] = 0.0f;
            o[1] = vrow[j][0].y;
            o[2] = vrow[j][1].x;
            o[3] = vrow[j][1].y;
            o[4] = vrow[j][2].x;
            dA++;
        }
    }
}

// ---------------------------------------------------------------------------
// Fill v2: persistent grid-stride over TAIL QUADS ONLY. float4 stores.
// Region A tail: elements [nA*5, N5).  Region B tail: [N5 + nB*6, N5+N6).
// Boundary quad (tail start not 16B-aligned) patched with scalar stores.
// ---------------------------------------------------------------------------
#define FILL_BLOCKS 1184   // 8 blocks/SM x 148 SMs -> single wave
__global__ __launch_bounds__(256) void fill_kernel(float* __restrict__ out) {
    const int nA = g_tot[0];
    const int nB = g_tot[1];
    const unsigned a0 = (unsigned)nA * 5u;          // first tail element (A)
    const unsigned b0 = N5 + (unsigned)nB * 6u;     // first tail element (B)
    const unsigned aq  = a0 >> 2;                   // quad containing a0
    const unsigned bq  = b0 >> 2;
    const unsigned aqe = N5 >> 2;                   // N5 divisible by 4
    const unsigned bqe = (N5 + N6) >> 2;            // divisible by 4

    float4* o4 = (float4*)out;
    const float4 z4 = make_float4(0.f, 0.f, 0.f, 0.f);
    const unsigned tid = blockIdx.x * 256u + threadIdx.x;
    const unsigned stride = gridDim.x * 256u;

    for (unsigned i = aq + tid; i < aqe; i += stride) {
        if (i != aq || (a0 & 3u) == 0u) {
            o4[i] = z4;
        } else {
            #pragma unroll
            for (unsigned k = 0; k < 4; k++) {
                unsigned e = i * 4u + k;
                if (e >= a0) out[e] = 0.0f;
            }
        }
    }
    for (unsigned i = bq + tid; i < bqe; i += stride) {
        if (i != bq || (b0 & 3u) == 0u) {
            o4[i] = z4;
        } else {
            #pragma unroll
            for (unsigned k = 0; k < 4; k++) {
                unsigned e = i * 4u + k;
                if (e >= b0) out[e] = 0.0f;
            }
        }
    }
    if (tid == 0) {
        out[N5 + N6]      = (float)nA;
        out[N5 + N6 + 1u] = (float)nB;
    }
}

extern "C" void kernel_launch(void* const* d_in, const int* in_sizes, int n_in,
                              void* d_out, int out_size) {
    const float* det = (const float*)d_in[0];
    float* out = (float*)d_out;

    count_kernel<<<NBLK, THREADS>>>(det);
    scan_kernel<<<1, 1024>>>();
    scatter_kernel<<<NBLK, THREADS>>>(det, out);
    fill_kernel<<<FILL_BLOCKS, 256>>>(out);
}

// round 10
// speedup vs baseline: 1.7671x; 1.0159x over previous
#include <cuda_runtime.h>

#define R_ROWS 4194304
#define ROWS_PER_BLOCK 1024
#define NBLK (R_ROWS / ROWS_PER_BLOCK)   // 4096
#define THREADS 256
#define ITEMS 4                          // rows per thread (blocked -> stable order)

#define N5 (R_ROWS * 5u)                 // 20971520 floats (rois)
#define N6 (R_ROWS * 6u)                 // 25165824 floats (rois_full)

// Decoupled-lookback state: one u64 per tile.
//   bits [62,64): 0 = invalid, 1 = aggregate ready, 2 = inclusive prefix ready
//   bits [24,48): count A    bits [0,24): count B   (totals <= 2^22, no carry)
#define FLAG_AGG (1ull << 62)
#define FLAG_PRE (2ull << 62)
#define PAYLOAD  ((1ull << 48) - 1ull)

__device__ unsigned long long g_state[NBLK];
__device__ int g_tot[2];

// ---------------------------------------------------------------------------
// Reset tile-status (must run at the start of every launch / graph replay).
// ---------------------------------------------------------------------------
__global__ __launch_bounds__(1024) void clear_kernel() {
    int i = blockIdx.x * 1024 + threadIdx.x;
    if (i < NBLK) g_state[i] = 0ull;
}

// ---------------------------------------------------------------------------
// Single pass: load tile, predicate, intra-block scan, decoupled lookback
// for the global exclusive prefix, stable scatter. Input read ONCE.
// ---------------------------------------------------------------------------
__global__ __launch_bounds__(THREADS) void fused_kernel(const float* __restrict__ det,
                                                        float* __restrict__ out) {
    __shared__ float4 s4[ROWS_PER_BLOCK * 6 / 4];   // 24 KB
    __shared__ int wsum[THREADS / 32];
    __shared__ unsigned long long s_excl;

    const int blk = blockIdx.x;
    const float4* src = (const float4*)(det + (size_t)blk * ROWS_PER_BLOCK * 6);
    #pragma unroll
    for (int i = threadIdx.x; i < ROWS_PER_BLOCK * 6 / 4; i += THREADS)
        s4[i] = src[i];
    __syncthreads();

    const float* sr = (const float*)s4;
    const int r0 = threadIdx.x * ITEMS;

    float2 vrow[ITEMS][3];
    bool pa[ITEMS], pb[ITEMS];
    int cA = 0, cB = 0;
    #pragma unroll
    for (int j = 0; j < ITEMS; j++) {
        const float2* rp = (const float2*)(sr + (r0 + j) * 6);
        vrow[j][0] = rp[0];
        vrow[j][1] = rp[1];
        vrow[j][2] = rp[2];
        bool b = (vrow[j][2].y >= 0.35f);          // score
        bool a = b && (vrow[j][0].x == 0.0f);      // class id
        pa[j] = a; pb[j] = b;
        cA += a; cB += b;
    }

    // intra-block scan of packed (cntA<<16 | cntB)
    int packed = (cA << 16) | cB;
    int incp = packed;
    const int lane = threadIdx.x & 31, w = threadIdx.x >> 5;
    #pragma unroll
    for (int d = 1; d < 32; d <<= 1) {
        int o = __shfl_up_sync(0xffffffffu, incp, d);
        if (lane >= d) incp += o;
    }
    if (lane == 31) wsum[w] = incp;
    __syncthreads();

    // ---- warp 0: publish aggregate, look back for exclusive prefix ----
    if (threadIdx.x < 32) {
        int aggp = 0;
        #pragma unroll
        for (int i = 0; i < THREADS / 32; i++) aggp += wsum[i];
        const unsigned long long agg =
            ((unsigned long long)(unsigned)(aggp >> 16) << 24) |
            (unsigned long long)(unsigned)(aggp & 0xffff);

        volatile unsigned long long* st = (volatile unsigned long long*)g_state;

        if (blk == 0) {
            if (lane == 0) {
                s_excl = 0ull;
                st[0] = FLAG_PRE | agg;
            }
        } else {
            if (lane == 0) st[blk] = FLAG_AGG | agg;   // publish early

            unsigned long long run = 0;
            int base = blk - 1;
            for (;;) {
                const int idx = base - lane;
                unsigned long long s = FLAG_PRE;        // idx < 0 => prefix 0
                if (idx >= 0) {
                    do { s = st[idx]; } while ((s >> 62) == 0ull);
                }
                const unsigned pm =
                    __ballot_sync(0xffffffffu, (idx < 0) || ((s >> 62) == 2ull));
                if (pm) {
                    const int leader = __ffs(pm) - 1;   // nearest prefix
                    unsigned long long v = (lane <= leader) ? (s & PAYLOAD) : 0ull;
                    #pragma unroll
                    for (int d = 16; d > 0; d >>= 1)
                        v += __shfl_down_sync(0xffffffffu, v, d);
                    if (lane == 0) {
                        const unsigned long long excl = run + v;
                        s_excl = excl;
                        const unsigned long long inc = excl + agg;
                        st[blk] = FLAG_PRE | inc;
                        if (blk == NBLK - 1) {
                            g_tot[0] = (int)((inc >> 24) & 0xffffffull);
                            g_tot[1] = (int)(inc & 0xffffffull);
                        }
                    }
                    break;
                } else {
                    unsigned long long v = s & PAYLOAD;
                    #pragma unroll
                    for (int d = 16; d > 0; d >>= 1)
                        v += __shfl_xor_sync(0xffffffffu, v, d);
                    run += v;                            // all lanes hold total
                    base -= 32;
                }
            }
        }
    }
    __syncthreads();

    // per-thread global destinations
    int wbase = 0;
    #pragma unroll
    for (int i = 0; i < THREADS / 32; i++)
        if (i < w) wbase += wsum[i];
    const int exc = wbase + incp - packed;               // intra-block exclusive

    const unsigned long long excl = s_excl;
    int dA = (int)((excl >> 24) & 0xffffffull) + (exc >> 16);
    int dB = (int)(excl & 0xffffffull) + (exc & 0xffff);

    float* outFull = out + (size_t)N5;
    #pragma unroll
    for (int j = 0; j < ITEMS; j++) {
        if (pb[j]) {
            float2* o = (float2*)(outFull + (size_t)dB * 6);  // 24B stride, 8B aligned
            o[0] = vrow[j][0];
            o[1] = vrow[j][1];
            o[2] = vrow[j][2];
            dB++;
        }
        if (pa[j]) {
            float* o = out + (size_t)dA * 5;
            o[0] = 0.0f;
            o[1] = vrow[j][0].y;
            o[2] = vrow[j][1].x;
            o[3] = vrow[j][1].y;
            o[4] = vrow[j][2].x;
            dA++;
        }
    }
}

// ---------------------------------------------------------------------------
// Fill: persistent grid-stride over TAIL QUADS ONLY. float4 stores.
// ---------------------------------------------------------------------------
#define FILL_BLOCKS 1184   // 8 blocks/SM x 148 SMs -> single wave
__global__ __launch_bounds__(256) void fill_kernel(float* __restrict__ out) {
    const int nA = g_tot[0];
    const int nB = g_tot[1];
    const unsigned a0 = (unsigned)nA * 5u;          // first tail element (A)
    const unsigned b0 = N5 + (unsigned)nB * 6u;     // first tail element (B)
    const unsigned aq  = a0 >> 2;
    const unsigned bq  = b0 >> 2;
    const unsigned aqe = N5 >> 2;
    const unsigned bqe = (N5 + N6) >> 2;

    float4* o4 = (float4*)out;
    const float4 z4 = make_float4(0.f, 0.f, 0.f, 0.f);
    const unsigned tid = blockIdx.x * 256u + threadIdx.x;
    const unsigned stride = gridDim.x * 256u;

    for (unsigned i = aq + tid; i < aqe; i += stride) {
        if (i != aq || (a0 & 3u) == 0u) {
            o4[i] = z4;
        } else {
            #pragma unroll
            for (unsigned k = 0; k < 4; k++) {
                unsigned e = i * 4u + k;
                if (e >= a0) out[e] = 0.0f;
            }
        }
    }
    for (unsigned i = bq + tid; i < bqe; i += stride) {
        if (i != bq || (b0 & 3u) == 0u) {
            o4[i] = z4;
        } else {
            #pragma unroll
            for (unsigned k = 0; k < 4; k++) {
                unsigned e = i * 4u + k;
                if (e >= b0) out[e] = 0.0f;
            }
        }
    }
    if (tid == 0) {
        out[N5 + N6]      = (float)nA;
        out[N5 + N6 + 1u] = (float)nB;
    }
}

extern "C" void kernel_launch(void* const* d_in, const int* in_sizes, int n_in,
                              void* d_out, int out_size) {
    const float* det = (const float*)d_in[0];
    float* out = (float*)d_out;

    clear_kernel<<<(NBLK + 1023) / 1024, 1024>>>();
    fused_kernel<<<NBLK, THREADS>>>(det, out);
    fill_kernel<<<FILL_BLOCKS, 256>>>(out);
}

// round 11
// speedup vs baseline: 1.8419x; 1.0423x over previous
#include <cuda_runtime.h>
#include <cstdint>

#define R_ROWS 4194304
#define ROWS_PER_BLOCK 1024
#define NBLK (R_ROWS / ROWS_PER_BLOCK)   // 4096
#define THREADS 256
#define ITEMS 4                          // rows per thread (blocked -> stable order)
#define TILE_BYTES (ROWS_PER_BLOCK * 6 * 4)   // 24576

#define N5 (R_ROWS * 5u)                 // 20971520 floats (rois)
#define N6 (R_ROWS * 6u)                 // 25165824 floats (rois_full)

// Decoupled-lookback state: one u64 per tile.
//   bits [62,64): 0 = invalid, 1 = aggregate ready, 2 = inclusive prefix ready
//   bits [24,48): count A    bits [0,24): count B   (totals <= 2^22, no carry)
#define FLAG_AGG (1ull << 62)
#define FLAG_PRE (2ull << 62)
#define PAYLOAD  ((1ull << 48) - 1ull)

__device__ unsigned long long g_state[NBLK];   // zero-initialized at load; reset by fill_kernel
__device__ int g_tot[2];

__device__ __forceinline__ uint32_t smem_u32(const void* p) {
    uint32_t a;
    asm("{ .reg .u64 t; cvta.to.shared.u64 t, %1; cvt.u32.u64 %0, t; }" : "=r"(a) : "l"(p));
    return a;
}

// ---------------------------------------------------------------------------
// Single pass: bulk-copy tile to SMEM (cp.async.bulk), predicate, intra-block
// scan, decoupled lookback for global exclusive prefix, stable scatter.
// ---------------------------------------------------------------------------
__global__ __launch_bounds__(THREADS) void fused_kernel(const float* __restrict__ det,
                                                        float* __restrict__ out) {
    __shared__ alignas(128) float4 s4[TILE_BYTES / 16];   // 24 KB
    __shared__ alignas(8) unsigned long long s_mbar;
    __shared__ int wsum[THREADS / 32];
    __shared__ unsigned long long s_excl;

    const int blk = blockIdx.x;
    const uint32_t mbar = smem_u32(&s_mbar);
    const uint32_t sdst = smem_u32(s4);

    if (threadIdx.x == 0) {
        asm volatile("mbarrier.init.shared.b64 [%0], %1;" :: "r"(mbar), "r"(1) : "memory");
        asm volatile("mbarrier.arrive.expect_tx.shared.b64 _, [%0], %1;"
                     :: "r"(mbar), "r"((unsigned)TILE_BYTES) : "memory");
        const char* gsrc = (const char*)det + (size_t)blk * TILE_BYTES;
        asm volatile("cp.async.bulk.shared::cta.global.mbarrier::complete_tx::bytes "
                     "[%0], [%1], %2, [%3];"
                     :: "r"(sdst), "l"(gsrc), "r"((unsigned)TILE_BYTES), "r"(mbar)
                     : "memory");
    }
    __syncthreads();
    // wait for bulk copy (phase 0; fresh smem barrier each block)
    {
        uint32_t done;
        asm volatile("{\n\t.reg .pred p;\n\t"
                     "mbarrier.try_wait.parity.acquire.cta.shared::cta.b64 p, [%1], %2;\n\t"
                     "selp.b32 %0, 1, 0, p;\n\t}"
                     : "=r"(done) : "r"(mbar), "r"(0u) : "memory");
        if (!done) {
            asm volatile("{\n\t.reg .pred P1;\n\t"
                         "WL_%=:\n\t"
                         "mbarrier.try_wait.parity.acquire.cta.shared::cta.b64 P1, [%0], %1, 0x989680;\n\t"
                         "@P1 bra.uni WD_%=;\n\t"
                         "bra.uni WL_%=;\n\t"
                         "WD_%=:\n\t}"
                         :: "r"(mbar), "r"(0u) : "memory");
        }
    }

    const float* sr = (const float*)s4;
    const int r0 = threadIdx.x * ITEMS;

    float2 vrow[ITEMS][3];
    bool pa[ITEMS], pb[ITEMS];
    int cA = 0, cB = 0;
    #pragma unroll
    for (int j = 0; j < ITEMS; j++) {
        const float2* rp = (const float2*)(sr + (r0 + j) * 6);
        vrow[j][0] = rp[0];
        vrow[j][1] = rp[1];
        vrow[j][2] = rp[2];
        bool b = (vrow[j][2].y >= 0.35f);          // score
        bool a = b && (vrow[j][0].x == 0.0f);      // class id
        pa[j] = a; pb[j] = b;
        cA += a; cB += b;
    }

    // intra-block scan of packed (cntA<<16 | cntB)
    int packed = (cA << 16) | cB;
    int incp = packed;
    const int lane = threadIdx.x & 31, w = threadIdx.x >> 5;
    #pragma unroll
    for (int d = 1; d < 32; d <<= 1) {
        int o = __shfl_up_sync(0xffffffffu, incp, d);
        if (lane >= d) incp += o;
    }
    if (lane == 31) wsum[w] = incp;
    __syncthreads();

    // ---- warp 0: publish aggregate, look back for exclusive prefix ----
    if (threadIdx.x < 32) {
        int aggp = 0;
        #pragma unroll
        for (int i = 0; i < THREADS / 32; i++) aggp += wsum[i];
        const unsigned long long agg =
            ((unsigned long long)(unsigned)(aggp >> 16) << 24) |
            (unsigned long long)(unsigned)(aggp & 0xffff);

        volatile unsigned long long* st = (volatile unsigned long long*)g_state;

        if (blk == 0) {
            if (lane == 0) {
                s_excl = 0ull;
                st[0] = FLAG_PRE | agg;
            }
        } else {
            if (lane == 0) st[blk] = FLAG_AGG | agg;   // publish early

            unsigned long long run = 0;
            int base = blk - 1;
            for (;;) {
                const int idx = base - lane;
                unsigned long long s = FLAG_PRE;        // idx < 0 => prefix 0
                if (idx >= 0) {
                    do { s = st[idx]; } while ((s >> 62) == 0ull);
                }
                const unsigned pm =
                    __ballot_sync(0xffffffffu, (idx < 0) || ((s >> 62) == 2ull));
                if (pm) {
                    const int leader = __ffs(pm) - 1;   // nearest prefix
                    unsigned long long v = (lane <= leader) ? (s & PAYLOAD) : 0ull;
                    #pragma unroll
                    for (int d = 16; d > 0; d >>= 1)
                        v += __shfl_down_sync(0xffffffffu, v, d);
                    if (lane == 0) {
                        const unsigned long long excl = run + v;
                        s_excl = excl;
                        const unsigned long long inc = excl + agg;
                        st[blk] = FLAG_PRE | inc;
                        if (blk == NBLK - 1) {
                            g_tot[0] = (int)((inc >> 24) & 0xffffffull);
                            g_tot[1] = (int)(inc & 0xffffffull);
                        }
                    }
                    break;
                } else {
                    unsigned long long v = s & PAYLOAD;
                    #pragma unroll
                    for (int d = 16; d > 0; d >>= 1)
                        v += __shfl_xor_sync(0xffffffffu, v, d);
                    run += v;                            // all lanes hold total
                    base -= 32;
                }
            }
        }
    }
    __syncthreads();

    // per-thread global destinations
    int wbase = 0;
    #pragma unroll
    for (int i = 0; i < THREADS / 32; i++)
        if (i < w) wbase += wsum[i];
    const int exc = wbase + incp - packed;               // intra-block exclusive

    const unsigned long long excl = s_excl;
    int dA = (int)((excl >> 24) & 0xffffffull) + (exc >> 16);
    int dB = (int)(excl & 0xffffffull) + (exc & 0xffff);

    float* outFull = out + (size_t)N5;
    #pragma unroll
    for (int j = 0; j < ITEMS; j++) {
        if (pb[j]) {
            float2* o = (float2*)(outFull + (size_t)dB * 6);  // 24B stride, 8B aligned
            o[0] = vrow[j][0];
            o[1] = vrow[j][1];
            o[2] = vrow[j][2];
            dB++;
        }
        if (pa[j]) {
            float* o = out + (size_t)dA * 5;
            o[0] = 0.0f;
            o[1] = vrow[j][0].y;
            o[2] = vrow[j][1].x;
            o[3] = vrow[j][1].y;
            o[4] = vrow[j][2].x;
            dA++;
        }
    }
}

// ---------------------------------------------------------------------------
// Fill: persistent grid-stride over TAIL QUADS ONLY + reset lookback state
// for the next graph replay (runs after fused_kernel, so this is safe).
// ---------------------------------------------------------------------------
#define FILL_BLOCKS 1184   // 8 blocks/SM x 148 SMs -> single wave
__global__ __launch_bounds__(256) void fill_kernel(float* __restrict__ out) {
    const unsigned tid = blockIdx.x * 256u + threadIdx.x;
    const unsigned stride = gridDim.x * 256u;

    if (tid < NBLK) g_state[tid] = 0ull;          // reset for next replay

    const int nA = g_tot[0];
    const int nB = g_tot[1];
    const unsigned a0 = (unsigned)nA * 5u;          // first tail element (A)
    const unsigned b0 = N5 + (unsigned)nB * 6u;     // first tail element (B)
    const unsigned aq  = a0 >> 2;
    const unsigned bq  = b0 >> 2;
    const unsigned aqe = N5 >> 2;
    const unsigned bqe = (N5 + N6) >> 2;

    float4* o4 = (float4*)out;
    const float4 z4 = make_float4(0.f, 0.f, 0.f, 0.f);

    for (unsigned i = aq + tid; i < aqe; i += stride) {
        if (i != aq || (a0 & 3u) == 0u) {
            o4[i] = z4;
        } else {
            #pragma unroll
            for (unsigned k = 0; k < 4; k++) {
                unsigned e = i * 4u + k;
                if (e >= a0) out[e] = 0.0f;
            }
        }
    }
    for (unsigned i = bq + tid; i < bqe; i += stride) {
        if (i != bq || (b0 & 3u) == 0u) {
            o4[i] = z4;
        } else {
            #pragma unroll
            for (unsigned k = 0; k < 4; k++) {
                unsigned e = i * 4u + k;
                if (e >= b0) out[e] = 0.0f;
            }
        }
    }
    if (tid == 0) {
        out[N5 + N6]      = (float)g_tot[0];
        out[N5 + N6 + 1u] = (float)g_tot[1];
    }
}

extern "C" void kernel_launch(void* const* d_in, const int* in_sizes, int n_in,
                              void* d_out, int out_size) {
    const float* det = (const float*)d_in[0];
    float* out = (float*)d_out;

    fused_kernel<<<NBLK, THREADS>>>(det, out);
    fill_kernel<<<FILL_BLOCKS, 256>>>(out);
}

// round 15
// speedup vs baseline: 2.1203x; 1.1511x over previous
#include <cuda_runtime.h>
#include <cstdint>

#define R_ROWS 4194304
#define ROWS_PER_BLOCK 1024
#define NBLK (R_ROWS / ROWS_PER_BLOCK)   // 4096
#define THREADS 256
#define ITEMS 4                          // rows per thread (blocked -> stable order)
#define TILE_BYTES (ROWS_PER_BLOCK * 6 * 4)   // 24576

#define N5 (R_ROWS * 5u)                 // 20971520 floats (rois)
#define N6 (R_ROWS * 6u)                 // 25165824 floats (rois_full)

// staging layout inside the shared buffer (floats):
//   [0, 6144)        : input tile, then reused for compacted B rows (cntB*6)
//   [6144, 11264)    : compacted A rows (cntA*5)
#define STAGE_FLOATS 11264               // 45056 bytes

// Decoupled-lookback state: one u64 per tile.
//   bits [62,64): 0 = invalid, 1 = aggregate ready, 2 = inclusive prefix ready
//   bits [24,48): count A    bits [0,24): count B   (totals <= 2^22, no carry)
#define FLAG_AGG (1ull << 62)
#define FLAG_PRE (2ull << 62)
#define PAYLOAD  ((1ull << 48) - 1ull)

__device__ unsigned long long g_state[NBLK];   // zero at load; reset by fill_kernel
__device__ int g_tot[2];

__device__ __forceinline__ uint32_t smem_u32(const void* p) {
    uint32_t a;
    asm("{ .reg .u64 t; cvta.to.shared.u64 t, %1; cvt.u32.u64 %0, t; }" : "=r"(a) : "l"(p));
    return a;
}

// ---------------------------------------------------------------------------
// Single pass: bulk-copy tile to SMEM, predicate, intra-block scan, decoupled
// lookback, compact into SMEM staging, stream contiguous ranges to global.
// ---------------------------------------------------------------------------
__global__ __launch_bounds__(THREADS) void fused_kernel(const float* __restrict__ det,
                                                        float* __restrict__ out) {
    __shared__ alignas(128) float s_stage[STAGE_FLOATS];   // 44 KB (tile + staging)
    __shared__ alignas(8) unsigned long long s_mbar;
    __shared__ int wsum[THREADS / 32];
    __shared__ int s_agg;
    __shared__ unsigned long long s_excl;

    const int blk = blockIdx.x;
    const uint32_t mbar = smem_u32(&s_mbar);
    const uint32_t sdst = smem_u32(s_stage);

    if (threadIdx.x == 0) {
        asm volatile("mbarrier.init.shared.b64 [%0], %1;" :: "r"(mbar), "r"(1) : "memory");
        asm volatile("mbarrier.arrive.expect_tx.shared.b64 _, [%0], %1;"
                     :: "r"(mbar), "r"((unsigned)TILE_BYTES) : "memory");
        const char* gsrc = (const char*)det + (size_t)blk * TILE_BYTES;
        asm volatile("cp.async.bulk.shared::cta.global.mbarrier::complete_tx::bytes "
                     "[%0], [%1], %2, [%3];"
                     :: "r"(sdst), "l"(gsrc), "r"((unsigned)TILE_BYTES), "r"(mbar)
                     : "memory");
    }
    __syncthreads();
    {   // wait for bulk copy (phase 0; fresh smem barrier each block)
        uint32_t done;
        asm volatile("{\n\t.reg .pred p;\n\t"
                     "mbarrier.try_wait.parity.acquire.cta.shared::cta.b64 p, [%1], %2;\n\t"
                     "selp.b32 %0, 1, 0, p;\n\t}"
                     : "=r"(done) : "r"(mbar), "r"(0u) : "memory");
        if (!done) {
            asm volatile("{\n\t.reg .pred P1;\n\t"
                         "WL_%=:\n\t"
                         "mbarrier.try_wait.parity.acquire.cta.shared::cta.b64 P1, [%0], %1, 0x989680;\n\t"
                         "@P1 bra.uni WD_%=;\n\t"
                         "bra.uni WL_%=;\n\t"
                         "WD_%=:\n\t}"
                         :: "r"(mbar), "r"(0u) : "memory");
        }
    }

    const float* sr = s_stage;
    const int r0 = threadIdx.x * ITEMS;

    float2 vrow[ITEMS][3];
    bool pa[ITEMS], pb[ITEMS];
    int cA = 0, cB = 0;
    #pragma unroll
    for (int j = 0; j < ITEMS; j++) {
        const float2* rp = (const float2*)(sr + (r0 + j) * 6);
        vrow[j][0] = rp[0];
        vrow[j][1] = rp[1];
        vrow[j][2] = rp[2];
        bool b = (vrow[j][2].y >= 0.35f);          // score
        bool a = b && (vrow[j][0].x == 0.0f);      // class id
        pa[j] = a; pb[j] = b;
        cA += a; cB += b;
    }

    // intra-block scan of packed (cntA<<16 | cntB)
    int packed = (cA << 16) | cB;
    int incp = packed;
    const int lane = threadIdx.x & 31, w = threadIdx.x >> 5;
    #pragma unroll
    for (int d = 1; d < 32; d <<= 1) {
        int o = __shfl_up_sync(0xffffffffu, incp, d);
        if (lane >= d) incp += o;
    }
    if (lane == 31) wsum[w] = incp;
    __syncthreads();   // also: last read of the input tile is above -> smem reusable

    // ---- warp 0: publish aggregate, look back for exclusive prefix ----
    if (threadIdx.x < 32) {
        int aggp = 0;
        #pragma unroll
        for (int i = 0; i < THREADS / 32; i++) aggp += wsum[i];
        if (lane == 0) s_agg = aggp;
        const unsigned long long agg =
            ((unsigned long long)(unsigned)(aggp >> 16) << 24) |
            (unsigned long long)(unsigned)(aggp & 0xffff);

        volatile unsigned long long* st = (volatile unsigned long long*)g_state;

        if (blk == 0) {
            if (lane == 0) {
                s_excl = 0ull;
                st[0] = FLAG_PRE | agg;
            }
        } else {
            if (lane == 0) st[blk] = FLAG_AGG | agg;   // publish early

            unsigned long long run = 0;
            int base = blk - 1;
            for (;;) {
                const int idx = base - lane;
                unsigned long long s = FLAG_PRE;        // idx < 0 => prefix 0
                if (idx >= 0) {
                    s = st[idx];
                    while ((s >> 62) == 0ull) { __nanosleep(40); s = st[idx]; }
                }
                const unsigned pm =
                    __ballot_sync(0xffffffffu, (idx < 0) || ((s >> 62) == 2ull));
                if (pm) {
                    const int leader = __ffs(pm) - 1;   // nearest prefix
                    unsigned long long v = (lane <= leader) ? (s & PAYLOAD) : 0ull;
                    #pragma unroll
                    for (int d = 16; d > 0; d >>= 1)
                        v += __shfl_down_sync(0xffffffffu, v, d);
                    if (lane == 0) {
                        const unsigned long long excl = run + v;
                        s_excl = excl;
                        const unsigned long long inc = excl + agg;
                        st[blk] = FLAG_PRE | inc;
                        if (blk == NBLK - 1) {
                            g_tot[0] = (int)((inc >> 24) & 0xffffffull);
                            g_tot[1] = (int)(inc & 0xffffffull);
                        }
                    }
                    break;
                } else {
                    unsigned long long v = s & PAYLOAD;
                    #pragma unroll
                    for (int d = 16; d > 0; d >>= 1)
                        v += __shfl_xor_sync(0xffffffffu, v, d);
                    run += v;                            // all lanes hold total
                    base -= 32;
                }
            }
        }
    }

    // intra-block exclusive prefix for this thread (registers + wsum only)
    int wbase = 0;
    #pragma unroll
    for (int i = 0; i < THREADS / 32; i++)
        if (i < w) wbase += wsum[i];
    const int exc = wbase + incp - packed;

    // ---- compact into SMEM staging (input tile is dead now) ----
    {
        int tB = exc & 0xffff;
        int tA = exc >> 16;
        float* sB = s_stage;
        float* sA = s_stage + 6144;
        #pragma unroll
        for (int j = 0; j < ITEMS; j++) {
            if (pb[j]) {
                float* o = sB + tB * 6;
                o[0] = vrow[j][0].x; o[1] = vrow[j][0].y;
                o[2] = vrow[j][1].x; o[3] = vrow[j][1].y;
                o[4] = vrow[j][2].x; o[5] = vrow[j][2].y;
                tB++;
            }
            if (pa[j]) {
                float* o = sA + tA * 5;
                o[0] = 0.0f;
                o[1] = vrow[j][0].y;
                o[2] = vrow[j][1].x; o[3] = vrow[j][1].y;
                o[4] = vrow[j][2].x;
                tA++;
            }
        }
    }
    __syncthreads();   // staging complete; s_excl + s_agg visible

    // ---- stream contiguous ranges to global (fully coalesced) ----
    const unsigned long long excl = s_excl;
    const int aggp  = s_agg;
    const int cntB  = aggp & 0xffff;
    const int cntA  = aggp >> 16;
    const int gB    = (int)(excl & 0xffffffull);
    const int gA    = (int)((excl >> 24) & 0xffffffull);

    {
        float* dstB = out + (size_t)N5 + (size_t)gB * 6;
        const float* sB = s_stage;
        const int nB = cntB * 6;
        for (int i = threadIdx.x; i < nB; i += THREADS) dstB[i] = sB[i];

        float* dstA = out + (size_t)gA * 5;
        const float* sA = s_stage + 6144;
        const int nA = cntA * 5;
        for (int i = threadIdx.x; i < nA; i += THREADS) dstA[i] = sA[i];
    }
}

// ---------------------------------------------------------------------------
// Fill: persistent grid-stride over TAIL QUADS ONLY + reset lookback state
// for the next graph replay (runs after fused_kernel, so this is safe).
// ---------------------------------------------------------------------------
#define FILL_BLOCKS 1184   // 8 blocks/SM x 148 SMs -> single wave
__global__ __launch_bounds__(256) void fill_kernel(float* __restrict__ out) {
    const unsigned tid = blockIdx.x * 256u + threadIdx.x;
    const unsigned stride = gridDim.x * 256u;

    if (tid < NBLK) g_state[tid] = 0ull;          // reset for next replay

    const int nA = g_tot[0];
    const int nB = g_tot[1];
    const unsigned a0 = (unsigned)nA * 5u;          // first tail element (A)
    const unsigned b0 = N5 + (unsigned)nB * 6u;     // first tail element (B)
    const unsigned aq  = a0 >> 2;
    const unsigned bq  = b0 >> 2;
    const unsigned aqe = N5 >> 2;
    const unsigned bqe = (N5 + N6) >> 2;

    float4* o4 = (float4*)out;
    const float4 z4 = make_float4(0.f, 0.f, 0.f, 0.f);

    for (unsigned i = aq + tid; i < aqe; i += stride) {
        if (i != aq || (a0 & 3u) == 0u) {
            o4[i] = z4;
        } else {
            #pragma unroll
            for (unsigned k = 0; k < 4; k++) {
                unsigned e = i * 4u + k;
                if (e >= a0) out[e] = 0.0f;
            }
        }
    }
    for (unsigned i = bq + tid; i < bqe; i += stride) {
        if (i != bq || (b0 & 3u) == 0u) {
            o4[i] = z4;
        } else {
            #pragma unroll
            for (unsigned k = 0; k < 4; k++) {
                unsigned e = i * 4u + k;
                if (e >= b0) out[e] = 0.0f;
            }
        }
    }
    if (tid == 0) {
        out[N5 + N6]      = (float)g_tot[0];
        out[N5 + N6 + 1u] = (float)g_tot[1];
    }
}

extern "C" void kernel_launch(void* const* d_in, const int* in_sizes, int n_in,
                              void* d_out, int out_size) {
    const float* det = (const float*)d_in[0];
    float* out = (float*)d_out;

    fused_kernel<<<NBLK, THREADS>>>(det, out);
    fill_kernel<<<FILL_BLOCKS, 256>>>(out);
}